// round 1
// baseline (speedup 1.0000x reference)
#include <cuda_runtime.h>
#include <cstdint>

#define BATCH 65536

// ---------------- static device scratch (no allocations) ----------------
__device__ __align__(16) float g_x[64 * BATCH];   // conv embedding, transposed [k][B]
__device__ __align__(16) float g_wt[98304];       // [cell][side][q][k][48]
__device__ __align__(16) float g_bias[1024];      // [cell][{r,z,ni,nh}][64]
__device__ __align__(16) float g_heads[8580];     // transposed head weights + biases

struct Params { const float* p[32]; };

// ---------------- prep: weight transposition ----------------
__global__ void prep_kernel(Params P) {
    int t = blockIdx.x * blockDim.x + threadIdx.x;
    if (t < 98304) {
        int cell = t / 24576, r1 = t % 24576;
        int side = r1 / 12288, r2 = r1 % 12288;
        int q    = r2 / 3072,  r3 = r2 % 3072;
        int k    = r3 / 48,    w  = r3 % 48;
        int g    = w / 16,     jj = w % 16;
        int row  = g * 64 + q * 16 + jj;
        const float* src = P.p[8 + cell * 4 + side];  // wih at +0, whh at +1
        g_wt[t] = src[row * 64 + k];
    } else if (t < 99328) {
        int u = t - 98304;
        int cell = u / 256, v = u % 256;
        int g4 = v / 64, j = v % 64;
        const float* bih = P.p[10 + cell * 4];
        const float* bhh = P.p[11 + cell * 4];
        float val;
        if      (g4 == 0) val = bih[j]       + bhh[j];        // r
        else if (g4 == 1) val = bih[64 + j]  + bhh[64 + j];   // z
        else if (g4 == 2) val = bih[128 + j];                 // i_n
        else              val = bhh[128 + j];                 // h_n
        g_bias[u] = val;
    } else if (t < 107908) {
        int u = t - 99328;
        float val;
        if      (u < 4096) { int k = u / 64, j = u % 64;      val = P.p[24][j * 64 + k]; } // actor_w1^T
        else if (u < 8192) { int z = u - 4096; int k = z / 64, j = z % 64; val = P.p[28][j * 64 + k]; } // critic_w1^T
        else if (u < 8384) { val = P.p[26][u - 8192]; }       // actor_w2 [3][64]
        else if (u < 8448) { val = P.p[30][u - 8384]; }       // critic_w2 [64]
        else if (u < 8512) { val = P.p[25][u - 8448]; }       // actor_b1
        else if (u < 8576) { val = P.p[29][u - 8512]; }       // critic_b1
        else if (u < 8579) { val = P.p[27][u - 8576]; }       // actor_b2
        else               { val = P.p[31][0]; }              // critic_b2
        g_heads[u] = val;
    }
}

// ---------------- conv: obs [B,7,7,3] -> embedding [64] ----------------
__global__ __launch_bounds__(128, 2)
void conv_kernel(const float* __restrict__ obs,
                 const float* __restrict__ w1, const float* __restrict__ b1,
                 const float* __restrict__ w2, const float* __restrict__ b2,
                 const float* __restrict__ w3, const float* __restrict__ b3) {
    __shared__ __align__(16) float sw1[192];
    __shared__ __align__(16) float sb1[16];
    __shared__ __align__(16) float sw2[2048];
    __shared__ __align__(16) float sb2[32];
    __shared__ __align__(16) float sw3[8192];
    __shared__ __align__(16) float sb3[64];

    int tid = threadIdx.x;
    for (int i = tid; i < 192;  i += 128) sw1[i] = w1[i];
    if (tid < 16) sb1[tid] = b1[tid];
    for (int i = tid; i < 2048; i += 128) sw2[i] = w2[i];
    if (tid < 32) sb2[tid] = b2[tid];
    for (int i = tid; i < 8192; i += 128) sw3[i] = w3[i];
    if (tid < 64) sb3[tid] = b3[tid];
    __syncthreads();

    int b = blockIdx.x * 128 + tid;
    const float* ob = obs + (size_t)b * 147;

    // conv1 (2x2, 3->16) + ReLU + maxpool 2x2  -> p1[16][3x3]
    float p1[16][9];
#pragma unroll
    for (int py = 0; py < 3; py++) {
#pragma unroll
        for (int px = 0; px < 3; px++) {
            float w[3][3][3];
#pragma unroll
            for (int dy = 0; dy < 3; dy++)
#pragma unroll
                for (int dx = 0; dx < 3; dx++)
#pragma unroll
                    for (int c = 0; c < 3; c++)
                        w[dy][dx][c] = __ldg(&ob[((2 * py + dy) * 7 + (2 * px + dx)) * 3 + c]);
#pragma unroll
            for (int oc = 0; oc < 16; oc++) {
                float wk[12];
#pragma unroll
                for (int i = 0; i < 12; i++) wk[i] = sw1[oc * 12 + i];
                float bb = sb1[oc];
                float m = 0.f;  // ReLU folded into pool: max(0, ...)
#pragma unroll
                for (int a = 0; a < 2; a++) {
#pragma unroll
                    for (int bb2 = 0; bb2 < 2; bb2++) {
                        float v = bb;
#pragma unroll
                        for (int c = 0; c < 3; c++)
#pragma unroll
                            for (int ky = 0; ky < 2; ky++)
#pragma unroll
                                for (int kx = 0; kx < 2; kx++)
                                    v += w[a + ky][bb2 + kx][c] * wk[c * 4 + ky * 2 + kx];
                        m = fmaxf(m, v);
                    }
                }
                p1[oc][py * 3 + px] = m;
            }
        }
    }

    // conv2 (2x2, 16->32) + ReLU -> c2[32][2x2]
    const float4* sw2_4 = reinterpret_cast<const float4*>(sw2);
    float c2[32][4];
#pragma unroll
    for (int qy = 0; qy < 2; qy++) {
#pragma unroll
        for (int qx = 0; qx < 2; qx++) {
#pragma unroll
            for (int oc = 0; oc < 32; oc++) {
                float a0 = sb2[oc], a1 = 0.f;
#pragma unroll
                for (int ic = 0; ic < 16; ic += 2) {
                    float4 wv = sw2_4[oc * 16 + ic];
                    a0 += p1[ic][qy * 3 + qx] * wv.x;
                    a0 += p1[ic][qy * 3 + qx + 1] * wv.y;
                    a0 += p1[ic][(qy + 1) * 3 + qx] * wv.z;
                    a0 += p1[ic][(qy + 1) * 3 + qx + 1] * wv.w;
                    float4 wu = sw2_4[oc * 16 + ic + 1];
                    a1 += p1[ic + 1][qy * 3 + qx] * wu.x;
                    a1 += p1[ic + 1][qy * 3 + qx + 1] * wu.y;
                    a1 += p1[ic + 1][(qy + 1) * 3 + qx] * wu.z;
                    a1 += p1[ic + 1][(qy + 1) * 3 + qx + 1] * wu.w;
                }
                c2[oc][qy * 2 + qx] = fmaxf(a0 + a1, 0.f);
            }
        }
    }

    // conv3 (2x2, 32->64) + ReLU -> embedding, stored transposed g_x[k][B]
    const float4* sw3_4 = reinterpret_cast<const float4*>(sw3);
#pragma unroll
    for (int oc = 0; oc < 64; oc++) {
        float a0 = sb3[oc], a1 = 0.f;
#pragma unroll
        for (int ic = 0; ic < 32; ic += 2) {
            float4 wv = sw3_4[oc * 32 + ic];
            a0 += c2[ic][0] * wv.x; a0 += c2[ic][1] * wv.y;
            a0 += c2[ic][2] * wv.z; a0 += c2[ic][3] * wv.w;
            float4 wu = sw3_4[oc * 32 + ic + 1];
            a1 += c2[ic + 1][0] * wu.x; a1 += c2[ic + 1][1] * wu.y;
            a1 += c2[ic + 1][2] * wu.z; a1 += c2[ic + 1][3] * wu.w;
        }
        g_x[oc * BATCH + b] = fmaxf(a0 + a1, 0.f);
    }
}

// ---------------- GRU x4 + actor/critic heads ----------------
__global__ __launch_bounds__(256)
void gru_kernel(const float* __restrict__ mem_in, float* __restrict__ out) {
    extern __shared__ __align__(16) float sm[];  // 24832 floats (cell) / 8580 (heads)
    int tid = threadIdx.x;
    int b = blockIdx.x * 256 + tid;

    float x[64], xn[64];
#pragma unroll 8
    for (int k = 0; k < 64; k++) x[k] = g_x[k * BATCH + b];

    const float* hb = mem_in + (size_t)b * 256;
    float* omem = out + (size_t)BATCH * 4 + (size_t)b * 256;

    for (int cell = 0; cell < 4; cell++) {
        __syncthreads();
        {   // stage cell weights + biases into smem
            const float4* src = reinterpret_cast<const float4*>(g_wt + cell * 24576);
            float4* dst = reinterpret_cast<float4*>(sm);
            for (int i = tid; i < 6144; i += 256) dst[i] = src[i];
            if (tid < 64)
                reinterpret_cast<float4*>(sm + 24576)[tid] =
                    reinterpret_cast<const float4*>(g_bias + cell * 256)[tid];
        }
        __syncthreads();

        const float* hcell = hb + cell * 64;
        for (int q = 0; q < 4; q++) {
            float ra[16], za[16], na[16], ha[16];
#pragma unroll
            for (int jj = 0; jj < 16; jj++) {
                ra[jj] = sm[24576 +       q * 16 + jj];
                za[jj] = sm[24576 + 64  + q * 16 + jj];
                na[jj] = sm[24576 + 128 + q * 16 + jj];
                ha[jj] = sm[24576 + 192 + q * 16 + jj];
            }
            const float4* wih = reinterpret_cast<const float4*>(sm) + q * 768;
            const float4* whh = wih + 3072;

            // x-pass: accumulate i_r, i_z, i_n
#pragma unroll 2
            for (int k = 0; k < 64; k++) {
                float xk = x[k];
                const float4* wp = wih + k * 12;
#pragma unroll
                for (int t4 = 0; t4 < 4; t4++) {
                    float4 w = wp[t4];
                    ra[t4*4+0] += xk * w.x; ra[t4*4+1] += xk * w.y;
                    ra[t4*4+2] += xk * w.z; ra[t4*4+3] += xk * w.w;
                }
#pragma unroll
                for (int t4 = 0; t4 < 4; t4++) {
                    float4 w = wp[4 + t4];
                    za[t4*4+0] += xk * w.x; za[t4*4+1] += xk * w.y;
                    za[t4*4+2] += xk * w.z; za[t4*4+3] += xk * w.w;
                }
#pragma unroll
                for (int t4 = 0; t4 < 4; t4++) {
                    float4 w = wp[8 + t4];
                    na[t4*4+0] += xk * w.x; na[t4*4+1] += xk * w.y;
                    na[t4*4+2] += xk * w.z; na[t4*4+3] += xk * w.w;
                }
            }
            // h-pass: accumulate h_r, h_z and h_n (separate for reset gate)
#pragma unroll 2
            for (int k = 0; k < 64; k++) {
                float hk = __ldg(&hcell[k]);
                const float4* wp = whh + k * 12;
#pragma unroll
                for (int t4 = 0; t4 < 4; t4++) {
                    float4 w = wp[t4];
                    ra[t4*4+0] += hk * w.x; ra[t4*4+1] += hk * w.y;
                    ra[t4*4+2] += hk * w.z; ra[t4*4+3] += hk * w.w;
                }
#pragma unroll
                for (int t4 = 0; t4 < 4; t4++) {
                    float4 w = wp[4 + t4];
                    za[t4*4+0] += hk * w.x; za[t4*4+1] += hk * w.y;
                    za[t4*4+2] += hk * w.z; za[t4*4+3] += hk * w.w;
                }
#pragma unroll
                for (int t4 = 0; t4 < 4; t4++) {
                    float4 w = wp[8 + t4];
                    ha[t4*4+0] += hk * w.x; ha[t4*4+1] += hk * w.y;
                    ha[t4*4+2] += hk * w.z; ha[t4*4+3] += hk * w.w;
                }
            }
            // finalize 16 outputs
#pragma unroll
            for (int jj = 0; jj < 16; jj++) {
                float r = __fdividef(1.f, 1.f + __expf(-ra[jj]));
                float z = __fdividef(1.f, 1.f + __expf(-za[jj]));
                float e = __expf(2.f * (na[jj] + r * ha[jj]));
                float n = 1.f - __fdividef(2.f, e + 1.f);   // tanh, saturation-safe
                float hj = __ldg(&hcell[q * 16 + jj]);
                float hn = (1.f - z) * n + z * hj;
                omem[cell * 64 + q * 16 + jj] = hn;
                xn[q * 16 + jj] = hn;
            }
        }
#pragma unroll 8
        for (int k = 0; k < 64; k++) x[k] = xn[k];
    }

    // ---------------- heads ----------------
    __syncthreads();
    {
        const float4* src = reinterpret_cast<const float4*>(g_heads);
        float4* dst = reinterpret_cast<float4*>(sm);
        for (int i = tid; i < 2145; i += 256) dst[i] = src[i];
    }
    __syncthreads();

    float lg0 = sm[8576], lg1 = sm[8577], lg2 = sm[8578];
    float v = sm[8579];
    for (int half = 0; half < 2; half++) {
        float aa[32], ca[32];
#pragma unroll
        for (int jj = 0; jj < 32; jj++) {
            aa[jj] = sm[8448 + half * 32 + jj];
            ca[jj] = sm[8512 + half * 32 + jj];
        }
        const float4* aw = reinterpret_cast<const float4*>(sm) + half * 8;
        const float4* cw = reinterpret_cast<const float4*>(sm + 4096) + half * 8;
#pragma unroll 2
        for (int k = 0; k < 64; k++) {
            float xk = x[k];
#pragma unroll
            for (int t4 = 0; t4 < 8; t4++) {
                float4 w = aw[k * 16 + t4];
                aa[t4*4+0] += xk * w.x; aa[t4*4+1] += xk * w.y;
                aa[t4*4+2] += xk * w.z; aa[t4*4+3] += xk * w.w;
                float4 w2 = cw[k * 16 + t4];
                ca[t4*4+0] += xk * w2.x; ca[t4*4+1] += xk * w2.y;
                ca[t4*4+2] += xk * w2.z; ca[t4*4+3] += xk * w2.w;
            }
        }
#pragma unroll
        for (int jj = 0; jj < 32; jj++) {
            int j = half * 32 + jj;
            float a = fmaxf(aa[jj], 0.f);
            lg0 += a * sm[8192 +       j];
            lg1 += a * sm[8192 + 64  + j];
            lg2 += a * sm[8192 + 128 + j];
            float c = fmaxf(ca[jj], 0.f);
            v += c * sm[8384 + j];
        }
    }
    float m = fmaxf(lg0, fmaxf(lg1, lg2));
    float s = __expf(lg0 - m) + __expf(lg1 - m) + __expf(lg2 - m);
    float lse = m + __logf(s);
    out[b * 3 + 0] = lg0 - lse;
    out[b * 3 + 1] = lg1 - lse;
    out[b * 3 + 2] = lg2 - lse;
    out[(size_t)BATCH * 3 + b] = v;
}

// ---------------- launch ----------------
extern "C" void kernel_launch(void* const* d_in, const int* in_sizes, int n_in,
                              void* d_out, int out_size) {
    Params P;
    for (int i = 0; i < 32; i++) P.p[i] = (const float*)d_in[i];
    float* out = (float*)d_out;

    cudaFuncSetAttribute(gru_kernel, cudaFuncAttributeMaxDynamicSharedMemorySize, 99328);

    prep_kernel<<<422, 256>>>(P);
    conv_kernel<<<BATCH / 128, 128>>>(P.p[0], P.p[2], P.p[3], P.p[4], P.p[5], P.p[6], P.p[7]);
    gru_kernel<<<BATCH / 256, 256, 99328>>>(P.p[1], out);
}

// round 3
// speedup vs baseline: 1.3918x; 1.3918x over previous
#include <cuda_runtime.h>
#include <cstdint>

#define BATCH 65536

// ---------------- static device scratch (no allocations) ----------------
__device__ __align__(16) float g_x[64 * BATCH];    // activation, transposed [k][B]
__device__ __align__(16) float g_h[256 * BATCH];   // memory transposed [j][B]
__device__ __align__(16) float g_wt[98304];        // [cell][side][q][k][48]
__device__ __align__(16) float g_bias[1024];       // [cell][{r,z,ni,nh}][64]
__device__ __align__(16) float g_heads[8580];      // transposed head weights + biases

struct Params { const float* p[32]; };

// ---------------- f32x2 helpers ----------------
__device__ __forceinline__ void ffma2(unsigned long long& acc, unsigned long long w,
                                      unsigned long long x) {
    asm("fma.rn.f32x2 %0, %1, %2, %0;" : "+l"(acc) : "l"(w), "l"(x));
}
__device__ __forceinline__ unsigned long long pack2(float a, float b) {
    unsigned long long r;
    asm("mov.b64 %0, {%1, %2};" : "=l"(r) : "f"(a), "f"(b));
    return r;
}
__device__ __forceinline__ void unpack2(unsigned long long v, float& a, float& b) {
    asm("mov.b64 {%0, %1}, %2;" : "=f"(a), "=f"(b) : "l"(v));
}

// ---------------- prep: weight transposition ----------------
__global__ void prep_kernel(Params P) {
    int t = blockIdx.x * blockDim.x + threadIdx.x;
    if (t < 98304) {
        int cell = t / 24576, r1 = t % 24576;
        int side = r1 / 12288, r2 = r1 % 12288;
        int q    = r2 / 3072,  r3 = r2 % 3072;
        int k    = r3 / 48,    w  = r3 % 48;
        int g    = w / 16,     jj = w % 16;
        int row  = g * 64 + q * 16 + jj;
        const float* src = P.p[8 + cell * 4 + side];  // wih at +0, whh at +1
        g_wt[t] = src[row * 64 + k];
    } else if (t < 99328) {
        int u = t - 98304;
        int cell = u / 256, v = u % 256;
        int g4 = v / 64, j = v % 64;
        const float* bih = P.p[10 + cell * 4];
        const float* bhh = P.p[11 + cell * 4];
        float val;
        if      (g4 == 0) val = bih[j]       + bhh[j];        // r
        else if (g4 == 1) val = bih[64 + j]  + bhh[64 + j];   // z
        else if (g4 == 2) val = bih[128 + j];                 // i_n
        else              val = bhh[128 + j];                 // h_n
        g_bias[u] = val;
    } else if (t < 107908) {
        int u = t - 99328;
        float val;
        if      (u < 4096) { int k = u / 64, j = u % 64;      val = P.p[24][j * 64 + k]; }
        else if (u < 8192) { int z = u - 4096; int k = z / 64, j = z % 64; val = P.p[28][j * 64 + k]; }
        else if (u < 8384) { val = P.p[26][u - 8192]; }       // actor_w2 [3][64]
        else if (u < 8448) { val = P.p[30][u - 8384]; }       // critic_w2 [64]
        else if (u < 8512) { val = P.p[25][u - 8448]; }       // actor_b1
        else if (u < 8576) { val = P.p[29][u - 8512]; }       // critic_b1
        else if (u < 8579) { val = P.p[27][u - 8576]; }       // actor_b2
        else               { val = P.p[31][0]; }              // critic_b2
        g_heads[u] = val;
    }
}

// ---------------- transpose: mem [B][256] -> g_h [256][B] ----------------
__global__ void transpose_kernel(const float* __restrict__ mem) {
    __shared__ float tile[32][33];
    int jb = blockIdx.y * 32;
    int bb = blockIdx.x * 32;
    int tx = threadIdx.x, ty = threadIdx.y;
#pragma unroll
    for (int r = ty; r < 32; r += 8)
        tile[r][tx] = mem[(size_t)(bb + r) * 256 + jb + tx];
    __syncthreads();
#pragma unroll
    for (int r = ty; r < 32; r += 8)
        g_h[(size_t)(jb + r) * BATCH + bb + tx] = tile[tx][r];
}

// ---------------- conv: obs [B,7,7,3] -> embedding [64] ----------------
__global__ __launch_bounds__(128, 2)
void conv_kernel(const float* __restrict__ obs,
                 const float* __restrict__ w1, const float* __restrict__ b1,
                 const float* __restrict__ w2, const float* __restrict__ b2,
                 const float* __restrict__ w3, const float* __restrict__ b3) {
    __shared__ __align__(16) float sw1[192];
    __shared__ __align__(16) float sb1[16];
    __shared__ __align__(16) float sw2[2048];
    __shared__ __align__(16) float sb2[32];
    __shared__ __align__(16) float sw3[8192];
    __shared__ __align__(16) float sb3[64];

    int tid = threadIdx.x;
    for (int i = tid; i < 192;  i += 128) sw1[i] = w1[i];
    if (tid < 16) sb1[tid] = b1[tid];
    for (int i = tid; i < 2048; i += 128) sw2[i] = w2[i];
    if (tid < 32) sb2[tid] = b2[tid];
    for (int i = tid; i < 8192; i += 128) sw3[i] = w3[i];
    if (tid < 64) sb3[tid] = b3[tid];
    __syncthreads();

    int b = blockIdx.x * 128 + tid;
    const float* ob = obs + (size_t)b * 147;

    float p1[16][9];
#pragma unroll
    for (int py = 0; py < 3; py++) {
#pragma unroll
        for (int px = 0; px < 3; px++) {
            float w[3][3][3];
#pragma unroll
            for (int dy = 0; dy < 3; dy++)
#pragma unroll
                for (int dx = 0; dx < 3; dx++)
#pragma unroll
                    for (int c = 0; c < 3; c++)
                        w[dy][dx][c] = __ldg(&ob[((2 * py + dy) * 7 + (2 * px + dx)) * 3 + c]);
#pragma unroll
            for (int oc = 0; oc < 16; oc++) {
                float wk[12];
#pragma unroll
                for (int i = 0; i < 12; i++) wk[i] = sw1[oc * 12 + i];
                float bb = sb1[oc];
                float m = 0.f;
#pragma unroll
                for (int a = 0; a < 2; a++) {
#pragma unroll
                    for (int bb2 = 0; bb2 < 2; bb2++) {
                        float v = bb;
#pragma unroll
                        for (int c = 0; c < 3; c++)
#pragma unroll
                            for (int ky = 0; ky < 2; ky++)
#pragma unroll
                                for (int kx = 0; kx < 2; kx++)
                                    v += w[a + ky][bb2 + kx][c] * wk[c * 4 + ky * 2 + kx];
                        m = fmaxf(m, v);
                    }
                }
                p1[oc][py * 3 + px] = m;
            }
        }
    }

    const float4* sw2_4 = reinterpret_cast<const float4*>(sw2);
    float c2[32][4];
#pragma unroll
    for (int qy = 0; qy < 2; qy++) {
#pragma unroll
        for (int qx = 0; qx < 2; qx++) {
#pragma unroll
            for (int oc = 0; oc < 32; oc++) {
                float a0 = sb2[oc], a1 = 0.f;
#pragma unroll
                for (int ic = 0; ic < 16; ic += 2) {
                    float4 wv = sw2_4[oc * 16 + ic];
                    a0 += p1[ic][qy * 3 + qx] * wv.x;
                    a0 += p1[ic][qy * 3 + qx + 1] * wv.y;
                    a0 += p1[ic][(qy + 1) * 3 + qx] * wv.z;
                    a0 += p1[ic][(qy + 1) * 3 + qx + 1] * wv.w;
                    float4 wu = sw2_4[oc * 16 + ic + 1];
                    a1 += p1[ic + 1][qy * 3 + qx] * wu.x;
                    a1 += p1[ic + 1][qy * 3 + qx + 1] * wu.y;
                    a1 += p1[ic + 1][(qy + 1) * 3 + qx] * wu.z;
                    a1 += p1[ic + 1][(qy + 1) * 3 + qx + 1] * wu.w;
                }
                c2[oc][qy * 2 + qx] = fmaxf(a0 + a1, 0.f);
            }
        }
    }

    const float4* sw3_4 = reinterpret_cast<const float4*>(sw3);
#pragma unroll
    for (int oc = 0; oc < 64; oc++) {
        float a0 = sb3[oc], a1 = 0.f;
#pragma unroll
        for (int ic = 0; ic < 32; ic += 2) {
            float4 wv = sw3_4[oc * 32 + ic];
            a0 += c2[ic][0] * wv.x; a0 += c2[ic][1] * wv.y;
            a0 += c2[ic][2] * wv.z; a0 += c2[ic][3] * wv.w;
            float4 wu = sw3_4[oc * 32 + ic + 1];
            a1 += c2[ic + 1][0] * wu.x; a1 += c2[ic + 1][1] * wu.y;
            a1 += c2[ic + 1][2] * wu.z; a1 += c2[ic + 1][3] * wu.w;
        }
        g_x[oc * BATCH + b] = fmaxf(a0 + a1, 0.f);
    }
}

// ---------------- GRU finalize helper ----------------
__device__ __forceinline__ void gru_fin(unsigned long long ra, unsigned long long za,
                                        unsigned long long na, unsigned long long ha,
                                        float h0, float h1, float& o0, float& o1) {
    float r0, r1, z0, z1, n0, n1, a0, a1;
    unpack2(ra, r0, r1); unpack2(za, z0, z1);
    unpack2(na, n0, n1); unpack2(ha, a0, a1);
    float rr0 = __fdividef(1.f, 1.f + __expf(-r0));
    float rr1 = __fdividef(1.f, 1.f + __expf(-r1));
    float zz0 = __fdividef(1.f, 1.f + __expf(-z0));
    float zz1 = __fdividef(1.f, 1.f + __expf(-z1));
    float e0 = __expf(2.f * (n0 + rr0 * a0));
    float e1 = __expf(2.f * (n1 + rr1 * a1));
    float nn0 = 1.f - __fdividef(2.f, e0 + 1.f);
    float nn1 = 1.f - __fdividef(2.f, e1 + 1.f);
    o0 = (1.f - zz0) * nn0 + zz0 * h0;
    o1 = (1.f - zz1) * nn1 + zz1 * h1;
}

// ---------------- GRU x4 + actor/critic heads ----------------
__global__ __launch_bounds__(256)
void gru_kernel(float* __restrict__ out) {
    extern __shared__ __align__(16) float sm[];  // 24832 floats
    int tid = threadIdx.x;
    int b = blockIdx.x * 256 + tid;

    float* omem = out + (size_t)BATCH * 4 + (size_t)b * 256;
    float x[64];

    for (int cell = 0; cell < 4; cell++) {
        __syncthreads();
        {   // stage cell weights + biases into smem
            const float4* src = reinterpret_cast<const float4*>(g_wt + cell * 24576);
            float4* dst = reinterpret_cast<float4*>(sm);
            for (int i = tid; i < 6144; i += 256) dst[i] = src[i];
            if (tid < 64)
                reinterpret_cast<float4*>(sm + 24576)[tid] =
                    reinterpret_cast<const float4*>(g_bias + cell * 256)[tid];
        }
        __syncthreads();

        // load current x (coalesced); same-thread RAW with the stores below
#pragma unroll 8
        for (int k = 0; k < 64; k++) x[k] = g_x[k * BATCH + b];

        const float* hrow = g_h + (size_t)cell * 64 * BATCH + b;   // stride BATCH per j
        const unsigned long long* bias2 =
            reinterpret_cast<const unsigned long long*>(sm + 24576);

        for (int q = 0; q < 4; q++) {
            unsigned long long ra[8], za[8], na[8], ha[8];
#pragma unroll
            for (int i = 0; i < 8; i++) {
                ra[i] = bias2[       q * 8 + i];
                za[i] = bias2[32  +  q * 8 + i];
                na[i] = bias2[64  +  q * 8 + i];
                ha[i] = bias2[96  +  q * 8 + i];
            }
            const ulonglong2* wx = reinterpret_cast<const ulonglong2*>(sm) + q * 768;
            const ulonglong2* wh = wx + 3072;

            // x-pass: i_r, i_z, i_n
#pragma unroll 4
            for (int k = 0; k < 64; k++) {
                unsigned long long xx = pack2(x[k], x[k]);
                const ulonglong2* wp = wx + k * 12;
                ulonglong2 w;
                w = wp[0];  ffma2(ra[0], w.x, xx); ffma2(ra[1], w.y, xx);
                w = wp[1];  ffma2(ra[2], w.x, xx); ffma2(ra[3], w.y, xx);
                w = wp[2];  ffma2(ra[4], w.x, xx); ffma2(ra[5], w.y, xx);
                w = wp[3];  ffma2(ra[6], w.x, xx); ffma2(ra[7], w.y, xx);
                w = wp[4];  ffma2(za[0], w.x, xx); ffma2(za[1], w.y, xx);
                w = wp[5];  ffma2(za[2], w.x, xx); ffma2(za[3], w.y, xx);
                w = wp[6];  ffma2(za[4], w.x, xx); ffma2(za[5], w.y, xx);
                w = wp[7];  ffma2(za[6], w.x, xx); ffma2(za[7], w.y, xx);
                w = wp[8];  ffma2(na[0], w.x, xx); ffma2(na[1], w.y, xx);
                w = wp[9];  ffma2(na[2], w.x, xx); ffma2(na[3], w.y, xx);
                w = wp[10]; ffma2(na[4], w.x, xx); ffma2(na[5], w.y, xx);
                w = wp[11]; ffma2(na[6], w.x, xx); ffma2(na[7], w.y, xx);
            }
            // h-pass: h_r, h_z, h_n (h read coalesced from g_h, L1-resident)
#pragma unroll 4
            for (int k = 0; k < 64; k++) {
                float hk = __ldg(&hrow[(size_t)k * BATCH]);
                unsigned long long hh = pack2(hk, hk);
                const ulonglong2* wp = wh + k * 12;
                ulonglong2 w;
                w = wp[0];  ffma2(ra[0], w.x, hh); ffma2(ra[1], w.y, hh);
                w = wp[1];  ffma2(ra[2], w.x, hh); ffma2(ra[3], w.y, hh);
                w = wp[2];  ffma2(ra[4], w.x, hh); ffma2(ra[5], w.y, hh);
                w = wp[3];  ffma2(ra[6], w.x, hh); ffma2(ra[7], w.y, hh);
                w = wp[4];  ffma2(za[0], w.x, hh); ffma2(za[1], w.y, hh);
                w = wp[5];  ffma2(za[2], w.x, hh); ffma2(za[3], w.y, hh);
                w = wp[6];  ffma2(za[4], w.x, hh); ffma2(za[5], w.y, hh);
                w = wp[7];  ffma2(za[6], w.x, hh); ffma2(za[7], w.y, hh);
                w = wp[8];  ffma2(ha[0], w.x, hh); ffma2(ha[1], w.y, hh);
                w = wp[9];  ffma2(ha[2], w.x, hh); ffma2(ha[3], w.y, hh);
                w = wp[10]; ffma2(ha[4], w.x, hh); ffma2(ha[5], w.y, hh);
                w = wp[11]; ffma2(ha[6], w.x, hh); ffma2(ha[7], w.y, hh);
            }
            // finalize 16 outputs: write next-x (coalesced) + memory_out (float4)
#pragma unroll
            for (int p4 = 0; p4 < 4; p4++) {
                int j0 = q * 16 + p4 * 4;
                float h0 = __ldg(&hrow[(size_t)(j0 + 0) * BATCH]);
                float h1 = __ldg(&hrow[(size_t)(j0 + 1) * BATCH]);
                float h2 = __ldg(&hrow[(size_t)(j0 + 2) * BATCH]);
                float h3 = __ldg(&hrow[(size_t)(j0 + 3) * BATCH]);
                float4 o;
                gru_fin(ra[p4 * 2],     za[p4 * 2],     na[p4 * 2],     ha[p4 * 2],     h0, h1, o.x, o.y);
                gru_fin(ra[p4 * 2 + 1], za[p4 * 2 + 1], na[p4 * 2 + 1], ha[p4 * 2 + 1], h2, h3, o.z, o.w);
                g_x[(j0 + 0) * BATCH + b] = o.x;
                g_x[(j0 + 1) * BATCH + b] = o.y;
                g_x[(j0 + 2) * BATCH + b] = o.z;
                g_x[(j0 + 3) * BATCH + b] = o.w;
                *reinterpret_cast<float4*>(omem + cell * 64 + j0) = o;
            }
        }
    }

    // ---------------- heads ----------------
    __syncthreads();
    {
        const float4* src = reinterpret_cast<const float4*>(g_heads);
        float4* dst = reinterpret_cast<float4*>(sm);
        for (int i = tid; i < 2145; i += 256) dst[i] = src[i];
    }
    __syncthreads();

    // reload final embedding (cell-3 output) from g_x (same-thread values)
#pragma unroll 8
    for (int k = 0; k < 64; k++) x[k] = g_x[k * BATCH + b];

    float lg0 = sm[8576], lg1 = sm[8577], lg2 = sm[8578];
    float v = sm[8579];
    const unsigned long long* hb2 = reinterpret_cast<const unsigned long long*>(sm + 8448);

    for (int half = 0; half < 2; half++) {
        unsigned long long aa[16], ca[16];
#pragma unroll
        for (int i = 0; i < 16; i++) {
            aa[i] = hb2[half * 16 + i];
            ca[i] = hb2[32 + half * 16 + i];
        }
        const ulonglong2* aw = reinterpret_cast<const ulonglong2*>(sm) + half * 8;
        const ulonglong2* cw = reinterpret_cast<const ulonglong2*>(sm + 4096) + half * 8;
#pragma unroll 4
        for (int k = 0; k < 64; k++) {
            unsigned long long xx = pack2(x[k], x[k]);
            const ulonglong2* ap = aw + k * 16;
            const ulonglong2* cp = cw + k * 16;
            ulonglong2 w;
            w = ap[0]; ffma2(aa[0],  w.x, xx); ffma2(aa[1],  w.y, xx);
            w = ap[1]; ffma2(aa[2],  w.x, xx); ffma2(aa[3],  w.y, xx);
            w = ap[2]; ffma2(aa[4],  w.x, xx); ffma2(aa[5],  w.y, xx);
            w = ap[3]; ffma2(aa[6],  w.x, xx); ffma2(aa[7],  w.y, xx);
            w = ap[4]; ffma2(aa[8],  w.x, xx); ffma2(aa[9],  w.y, xx);
            w = ap[5]; ffma2(aa[10], w.x, xx); ffma2(aa[11], w.y, xx);
            w = ap[6]; ffma2(aa[12], w.x, xx); ffma2(aa[13], w.y, xx);
            w = ap[7]; ffma2(aa[14], w.x, xx); ffma2(aa[15], w.y, xx);
            w = cp[0]; ffma2(ca[0],  w.x, xx); ffma2(ca[1],  w.y, xx);
            w = cp[1]; ffma2(ca[2],  w.x, xx); ffma2(ca[3],  w.y, xx);
            w = cp[2]; ffma2(ca[4],  w.x, xx); ffma2(ca[5],  w.y, xx);
            w = cp[3]; ffma2(ca[6],  w.x, xx); ffma2(ca[7],  w.y, xx);
            w = cp[4]; ffma2(ca[8],  w.x, xx); ffma2(ca[9],  w.y, xx);
            w = cp[5]; ffma2(ca[10], w.x, xx); ffma2(ca[11], w.y, xx);
            w = cp[6]; ffma2(ca[12], w.x, xx); ffma2(ca[13], w.y, xx);
            w = cp[7]; ffma2(ca[14], w.x, xx); ffma2(ca[15], w.y, xx);
        }
#pragma unroll
        for (int i = 0; i < 16; i++) {
            int j = half * 32 + i * 2;
            float a0, a1, c0, c1;
            unpack2(aa[i], a0, a1);
            unpack2(ca[i], c0, c1);
            a0 = fmaxf(a0, 0.f); a1 = fmaxf(a1, 0.f);
            c0 = fmaxf(c0, 0.f); c1 = fmaxf(c1, 0.f);
            lg0 += a0 * sm[8192 +       j] + a1 * sm[8192 +       j + 1];
            lg1 += a0 * sm[8192 + 64  + j] + a1 * sm[8192 + 64  + j + 1];
            lg2 += a0 * sm[8192 + 128 + j] + a1 * sm[8192 + 128 + j + 1];
            v   += c0 * sm[8384 + j]       + c1 * sm[8384 + j + 1];
        }
    }
    float m = fmaxf(lg0, fmaxf(lg1, lg2));
    float s = __expf(lg0 - m) + __expf(lg1 - m) + __expf(lg2 - m);
    float lse = m + __logf(s);
    out[b * 3 + 0] = lg0 - lse;
    out[b * 3 + 1] = lg1 - lse;
    out[b * 3 + 2] = lg2 - lse;
    out[(size_t)BATCH * 3 + b] = v;
}

// ---------------- launch ----------------
extern "C" void kernel_launch(void* const* d_in, const int* in_sizes, int n_in,
                              void* d_out, int out_size) {
    Params P;
    for (int i = 0; i < 32; i++) P.p[i] = (const float*)d_in[i];
    float* out = (float*)d_out;

    cudaFuncSetAttribute(gru_kernel, cudaFuncAttributeMaxDynamicSharedMemorySize, 99328);

    prep_kernel<<<422, 256>>>(P);
    transpose_kernel<<<dim3(BATCH / 32, 8), dim3(32, 8)>>>(P.p[1]);
    conv_kernel<<<BATCH / 128, 128>>>(P.p[0], P.p[2], P.p[3], P.p[4], P.p[5], P.p[6], P.p[7]);
    gru_kernel<<<BATCH / 256, 256, 99328>>>(out);
}

// round 8
// speedup vs baseline: 1.4218x; 1.0216x over previous
#include <cuda_runtime.h>
#include <cstdint>

#define BATCH 65536
typedef unsigned long long u64;

// ---------------- static device scratch (no allocations) ----------------
__device__ __align__(16) float g_x[64 * BATCH];    // conv embedding, transposed [k][B]
__device__ __align__(16) float g_h[256 * BATCH];   // memory transposed [j][B]
__device__ __align__(16) float g_wt[98304];        // [cell][side(x/h)][k][gate3][pair32][2]
__device__ __align__(16) float g_bias[1024];       // [cell][{r,z,ni,nh}][64]
__device__ __align__(16) float g_heads[8580];      // [k][64 pair-floats] + w2/b
struct Params { const float* p[32]; };

// ---------------- f32x2 helpers ----------------
__device__ __forceinline__ void ffma2(u64& acc, u64 w, u64 x) {
    asm("fma.rn.f32x2 %0, %1, %2, %0;" : "+l"(acc) : "l"(w), "l"(x));
}
__device__ __forceinline__ u64 pack2(float a, float b) {
    u64 r; asm("mov.b64 %0, {%1, %2};" : "=l"(r) : "f"(a), "f"(b)); return r;
}
__device__ __forceinline__ void unpack2(u64 v, float& a, float& b) {
    asm("mov.b64 {%0, %1}, %2;" : "=f"(a), "=f"(b) : "l"(v));
}
__device__ __forceinline__ float sigm(float v) {
    return __fdividef(1.f, 1.f + __expf(-v));
}
__device__ __forceinline__ float tanh_fast(float v) {
    float e = __expf(2.f * v);
    return 1.f - __fdividef(2.f, e + 1.f);
}

// ---------------- prep: weight transposition ----------------
__global__ void prep_kernel(Params P) {
    int t = blockIdx.x * blockDim.x + threadIdx.x;
    if (t < 98304) {
        // [cell][side][k][g][j(=pair*2+half)] ; val = src[(g*64+j)*64 + k]
        int cell = t / 24576, r1 = t % 24576;
        int side = r1 / 12288, r2 = r1 % 12288;
        int k    = r2 / 192,   r3 = r2 % 192;
        int g    = r3 / 64,    j  = r3 % 64;
        const float* src = P.p[8 + cell * 4 + side];  // wih, whh
        g_wt[t] = src[(g * 64 + j) * 64 + k];
    } else if (t < 99328) {
        int u = t - 98304;
        int cell = u / 256, v = u % 256;
        int g4 = v / 64, j = v % 64;
        const float* bih = P.p[10 + cell * 4];
        const float* bhh = P.p[11 + cell * 4];
        float val;
        if      (g4 == 0) val = bih[j]       + bhh[j];
        else if (g4 == 1) val = bih[64 + j]  + bhh[64 + j];
        else if (g4 == 2) val = bih[128 + j];
        else              val = bhh[128 + j];
        g_bias[u] = val;
    } else if (t < 107908) {
        int u = t - 99328;
        float val;
        if (u < 8192) {        // w1: [k][128] : pairs 0..31 actor, 32..63 critic
            int k = u / 128, f = u % 128;
            int pair = f / 2, half = f & 1;
            if (pair < 32) val = P.p[24][(2 * pair + half) * 64 + k];
            else           val = P.p[28][(2 * (pair - 32) + half) * 64 + k];
        }
        else if (u < 8384) val = P.p[26][u - 8192];   // actor_w2 [3][64]
        else if (u < 8448) val = P.p[30][u - 8384];   // critic_w2 [64]
        else if (u < 8512) val = P.p[25][u - 8448];   // actor_b1
        else if (u < 8576) val = P.p[29][u - 8512];   // critic_b1
        else if (u < 8579) val = P.p[27][u - 8576];   // actor_b2
        else               val = P.p[31][0];          // critic_b2
        g_heads[u] = val;
    }
}

// ---------------- transpose: mem [B][256] -> g_h [256][B] ----------------
__global__ void transpose_kernel(const float* __restrict__ mem) {
    __shared__ float tile[32][33];
    int jb = blockIdx.y * 32;
    int bb = blockIdx.x * 32;
    int tx = threadIdx.x, ty = threadIdx.y;
#pragma unroll
    for (int r = ty; r < 32; r += 8)
        tile[r][tx] = mem[(size_t)(bb + r) * 256 + jb + tx];
    __syncthreads();
#pragma unroll
    for (int r = ty; r < 32; r += 8)
        g_h[(size_t)(jb + r) * BATCH + bb + tx] = tile[tx][r];
}

// ---------------- conv: R3-proven structure + smem-staged obs ----------------
// smem: obs 37632 | w1 192 | b1 16 | w2 2048 | b2 32 | w3 8192 | b3 64 = 48176 floats
#define CONV_SMEM_FLOATS 48176
__global__ __launch_bounds__(256, 1)
void conv_kernel(const float* __restrict__ obs,
                 const float* __restrict__ w1, const float* __restrict__ b1,
                 const float* __restrict__ w2, const float* __restrict__ b2,
                 const float* __restrict__ w3, const float* __restrict__ b3) {
    extern __shared__ __align__(16) float cs[];
    float* obs_s = cs;                 // 37632
    float* sw1 = cs + 37632;           // 192
    float* sb1 = cs + 37824;           // 16
    float* sw2 = cs + 37840;           // 2048
    float* sb2 = cs + 39888;           // 32
    float* sw3 = cs + 39920;           // 8192
    float* sb3 = cs + 48112;           // 64
    int tid = threadIdx.x;

    { // stage obs block: 256 rows x 147 floats = 9408 float4 (coalesced)
        const float4* src = reinterpret_cast<const float4*>(obs) + (size_t)blockIdx.x * 9408;
        float4* dst = reinterpret_cast<float4*>(obs_s);
        for (int i = tid; i < 9408; i += 256) dst[i] = src[i];
    }
    for (int i = tid; i < 192;  i += 256) sw1[i] = w1[i];
    if (tid < 16) sb1[tid] = b1[tid];
    for (int i = tid; i < 2048; i += 256) sw2[i] = w2[i];
    if (tid < 32) sb2[tid] = b2[tid];
    for (int i = tid; i < 8192; i += 256) sw3[i] = w3[i];
    if (tid < 64) sb3[tid] = b3[tid];
    __syncthreads();

    int b = blockIdx.x * 256 + tid;
    const float* ob = obs_s + tid * 147;

    // conv1 (2x2, 3->16) + ReLU + maxpool 2x2 -> p1[16][3x3]
    float p1[16][9];
#pragma unroll
    for (int py = 0; py < 3; py++) {
#pragma unroll
        for (int px = 0; px < 3; px++) {
            float w[3][3][3];
#pragma unroll
            for (int dy = 0; dy < 3; dy++)
#pragma unroll
                for (int dx = 0; dx < 3; dx++)
#pragma unroll
                    for (int c = 0; c < 3; c++)
                        w[dy][dx][c] = ob[((2 * py + dy) * 7 + (2 * px + dx)) * 3 + c];
#pragma unroll
            for (int oc = 0; oc < 16; oc++) {
                float wk[12];
#pragma unroll
                for (int i = 0; i < 12; i++) wk[i] = sw1[oc * 12 + i];
                float bb = sb1[oc];
                float m = 0.f;  // ReLU folded into pool
#pragma unroll
                for (int a = 0; a < 2; a++) {
#pragma unroll
                    for (int bb2 = 0; bb2 < 2; bb2++) {
                        float v = bb;
#pragma unroll
                        for (int c = 0; c < 3; c++)
#pragma unroll
                            for (int ky = 0; ky < 2; ky++)
#pragma unroll
                                for (int kx = 0; kx < 2; kx++)
                                    v += w[a + ky][bb2 + kx][c] * wk[c * 4 + ky * 2 + kx];
                        m = fmaxf(m, v);
                    }
                }
                p1[oc][py * 3 + px] = m;
            }
        }
    }

    // conv2 (2x2, 16->32) + ReLU -> c2[32][4]
    const float4* sw2_4 = reinterpret_cast<const float4*>(sw2);
    float c2[32][4];
#pragma unroll
    for (int qy = 0; qy < 2; qy++) {
#pragma unroll
        for (int qx = 0; qx < 2; qx++) {
#pragma unroll
            for (int oc = 0; oc < 32; oc++) {
                float a0 = sb2[oc], a1 = 0.f;
#pragma unroll
                for (int ic = 0; ic < 16; ic += 2) {
                    float4 wv = sw2_4[oc * 16 + ic];
                    a0 += p1[ic][qy * 3 + qx] * wv.x;
                    a0 += p1[ic][qy * 3 + qx + 1] * wv.y;
                    a0 += p1[ic][(qy + 1) * 3 + qx] * wv.z;
                    a0 += p1[ic][(qy + 1) * 3 + qx + 1] * wv.w;
                    float4 wu = sw2_4[oc * 16 + ic + 1];
                    a1 += p1[ic + 1][qy * 3 + qx] * wu.x;
                    a1 += p1[ic + 1][qy * 3 + qx + 1] * wu.y;
                    a1 += p1[ic + 1][(qy + 1) * 3 + qx] * wu.z;
                    a1 += p1[ic + 1][(qy + 1) * 3 + qx + 1] * wu.w;
                }
                c2[oc][qy * 2 + qx] = fmaxf(a0 + a1, 0.f);
            }
        }
    }

    // conv3 (2x2 on 2x2 -> 1x1, 32->64) + ReLU, write transposed
    const float4* sw3_4 = reinterpret_cast<const float4*>(sw3);
#pragma unroll
    for (int oc = 0; oc < 64; oc++) {
        float a0 = sb3[oc], a1 = 0.f;
#pragma unroll
        for (int ic = 0; ic < 32; ic += 2) {
            float4 wv = sw3_4[oc * 32 + ic];
            a0 += c2[ic][0] * wv.x; a0 += c2[ic][1] * wv.y;
            a0 += c2[ic][2] * wv.z; a0 += c2[ic][3] * wv.w;
            float4 wu = sw3_4[oc * 32 + ic + 1];
            a1 += c2[ic + 1][0] * wu.x; a1 += c2[ic + 1][1] * wu.y;
            a1 += c2[ic + 1][2] * wu.z; a1 += c2[ic + 1][3] * wu.w;
        }
        g_x[oc * BATCH + b] = fmaxf(a0 + a1, 0.f);
    }
}

// ---------------- GRU x4 + heads : register-tiled GEMM ----------------
// smem: W 24576 | x_tile 4096 | h_tile 4096 | bias 256  = 33024 floats
#define GRU_SMEM_FLOATS 33024
__global__ __launch_bounds__(256, 1)
void gru_kernel(float* __restrict__ out) {
    extern __shared__ __align__(16) float sm[];
    float* xt = sm + 24576;
    float* ht = sm + 28672;
    float* bias = sm + 32768;
    int tid = threadIdx.x;
    int tj = tid >> 4, bq = tid & 15;        // thread: j = 4*tj..4*tj+3, b = bq*4..bq*4+3
    int tb = blockIdx.x * 64;

    { // stage x_tile from g_x (coalesced)
        float4* dst = reinterpret_cast<float4*>(xt);
        for (int i = tid; i < 1024; i += 256) {
            int row = i >> 4, c4 = i & 15;
            dst[i] = *reinterpret_cast<const float4*>(&g_x[row * BATCH + tb + c4 * 4]);
        }
    }

    for (int cell = 0; cell < 4; cell++) {
        __syncthreads();
        { // stage weights + h_tile + bias
            const float4* src = reinterpret_cast<const float4*>(g_wt + cell * 24576);
            float4* dst = reinterpret_cast<float4*>(sm);
            for (int i = tid; i < 6144; i += 256) dst[i] = src[i];
            float4* hdst = reinterpret_cast<float4*>(ht);
            for (int i = tid; i < 1024; i += 256) {
                int row = i >> 4, c4 = i & 15;
                hdst[i] = *reinterpret_cast<const float4*>(
                    &g_h[(size_t)(cell * 64 + row) * BATCH + tb + c4 * 4]);
            }
            if (tid < 64)
                reinterpret_cast<float4*>(bias)[tid] =
                    reinterpret_cast<const float4*>(g_bias + cell * 256)[tid];
        }
        __syncthreads();

        u64 ar[2][4], az[2][4], an[2][4], ah[2][4];
        {
            const u64* bs = reinterpret_cast<const u64*>(bias);
#pragma unroll
            for (int p = 0; p < 2; p++) {
                u64 vr = bs[      2 * tj + p];
                u64 vz = bs[32 +  2 * tj + p];
                u64 vn = bs[64 +  2 * tj + p];
                u64 vh = bs[96 +  2 * tj + p];
#pragma unroll
                for (int b = 0; b < 4; b++) { ar[p][b] = vr; az[p][b] = vz; an[p][b] = vn; ah[p][b] = vh; }
            }
        }

        const ulonglong2* Wx = reinterpret_cast<const ulonglong2*>(sm);
        const ulonglong2* Wh = Wx + 3072;
        const float4* xt4 = reinterpret_cast<const float4*>(xt);
        const float4* ht4 = reinterpret_cast<const float4*>(ht);

        // x-pass: r, z, ni
#pragma unroll 2
        for (int k = 0; k < 64; k++) {
            float4 xv = xt4[k * 16 + bq];
            u64 xp[4] = {pack2(xv.x, xv.x), pack2(xv.y, xv.y), pack2(xv.z, xv.z), pack2(xv.w, xv.w)};
            ulonglong2 wr = Wx[k * 48 +      tj];
            ulonglong2 wz = Wx[k * 48 + 16 + tj];
            ulonglong2 wn = Wx[k * 48 + 32 + tj];
            u64 wrp[2] = {wr.x, wr.y}, wzp[2] = {wz.x, wz.y}, wnp[2] = {wn.x, wn.y};
#pragma unroll
            for (int p = 0; p < 2; p++)
#pragma unroll
                for (int b = 0; b < 4; b++) {
                    ffma2(ar[p][b], wrp[p], xp[b]);
                    ffma2(az[p][b], wzp[p], xp[b]);
                    ffma2(an[p][b], wnp[p], xp[b]);
                }
        }
        // h-pass: r, z, nh
#pragma unroll 2
        for (int k = 0; k < 64; k++) {
            float4 hv = ht4[k * 16 + bq];
            u64 hp[4] = {pack2(hv.x, hv.x), pack2(hv.y, hv.y), pack2(hv.z, hv.z), pack2(hv.w, hv.w)};
            ulonglong2 wr = Wh[k * 48 +      tj];
            ulonglong2 wz = Wh[k * 48 + 16 + tj];
            ulonglong2 wn = Wh[k * 48 + 32 + tj];
            u64 wrp[2] = {wr.x, wr.y}, wzp[2] = {wz.x, wz.y}, wnp[2] = {wn.x, wn.y};
#pragma unroll
            for (int p = 0; p < 2; p++)
#pragma unroll
                for (int b = 0; b < 4; b++) {
                    ffma2(ar[p][b], wrp[p], hp[b]);
                    ffma2(az[p][b], wzp[p], hp[b]);
                    ffma2(ah[p][b], wnp[p], hp[b]);
                }
        }

        __syncthreads();   // all GEMM reads of xt done before overwrite
        // finalize
        float hpa[4][4];
#pragma unroll
        for (int jj = 0; jj < 4; jj++) {
            float4 hv = ht4[(4 * tj + jj) * 16 + bq];
            hpa[jj][0] = hv.x; hpa[jj][1] = hv.y; hpa[jj][2] = hv.z; hpa[jj][3] = hv.w;
        }
        float o[4][4];
#pragma unroll
        for (int p = 0; p < 2; p++) {
#pragma unroll
            for (int b = 0; b < 4; b++) {
                float r0, r1, z0, z1, n0, n1, q0, q1;
                unpack2(ar[p][b], r0, r1); unpack2(az[p][b], z0, z1);
                unpack2(an[p][b], n0, n1); unpack2(ah[p][b], q0, q1);
                float rr0 = sigm(r0), rr1 = sigm(r1);
                float zz0 = sigm(z0), zz1 = sigm(z1);
                float nn0 = tanh_fast(n0 + rr0 * q0);
                float nn1 = tanh_fast(n1 + rr1 * q1);
                o[2 * p][b]     = (1.f - zz0) * nn0 + zz0 * hpa[2 * p][b];
                o[2 * p + 1][b] = (1.f - zz1) * nn1 + zz1 * hpa[2 * p + 1][b];
            }
        }
        float4* xtw = reinterpret_cast<float4*>(xt);
#pragma unroll
        for (int jj = 0; jj < 4; jj++)
            xtw[(4 * tj + jj) * 16 + bq] = make_float4(o[jj][0], o[jj][1], o[jj][2], o[jj][3]);
#pragma unroll
        for (int b = 0; b < 4; b++) {
            size_t gb = (size_t)(tb + bq * 4 + b);
            *reinterpret_cast<float4*>(&out[(size_t)4 * BATCH + gb * 256 + cell * 64 + 4 * tj]) =
                make_float4(o[0][b], o[1][b], o[2][b], o[3][b]);
        }
    }

    // ---------------- heads ----------------
    __syncthreads();
    { // stage head weights into W region
        const float4* src = reinterpret_cast<const float4*>(g_heads);
        float4* dst = reinterpret_cast<float4*>(sm);
        for (int i = tid; i < 2145; i += 256) dst[i] = src[i];
    }
    __syncthreads();

    int bL = tid >> 2, part = tid & 3;      // b = tb+bL ; h-range = part*16..+16
    u64 aa[8], cc[8];
    {
        const u64* ba = reinterpret_cast<const u64*>(sm + 8448);
        const u64* bc = reinterpret_cast<const u64*>(sm + 8512);
#pragma unroll
        for (int i = 0; i < 8; i++) { aa[i] = ba[part * 8 + i]; cc[i] = bc[part * 8 + i]; }
    }
    const ulonglong2* w1 = reinterpret_cast<const ulonglong2*>(sm);
#pragma unroll 2
    for (int k = 0; k < 64; k++) {
        float xv = xt[k * 64 + bL];
        u64 xp = pack2(xv, xv);
        const ulonglong2* row = w1 + k * 32;
#pragma unroll
        for (int i2 = 0; i2 < 4; i2++) {
            ulonglong2 wa = row[part * 4 + i2];
            ffma2(aa[i2 * 2], wa.x, xp); ffma2(aa[i2 * 2 + 1], wa.y, xp);
            ulonglong2 wc = row[16 + part * 4 + i2];
            ffma2(cc[i2 * 2], wc.x, xp); ffma2(cc[i2 * 2 + 1], wc.y, xp);
        }
    }
    float lg0 = 0.f, lg1 = 0.f, lg2 = 0.f, vv = 0.f;
    {
        const float* w2a = sm + 8192;
        const float* w2c = sm + 8384;
#pragma unroll
        for (int i = 0; i < 8; i++) {
            float a0, a1, c0, c1;
            unpack2(aa[i], a0, a1); unpack2(cc[i], c0, c1);
            a0 = fmaxf(a0, 0.f); a1 = fmaxf(a1, 0.f);
            c0 = fmaxf(c0, 0.f); c1 = fmaxf(c1, 0.f);
            int h = part * 16 + 2 * i;
            lg0 += a0 * w2a[h]       + a1 * w2a[h + 1];
            lg1 += a0 * w2a[64 + h]  + a1 * w2a[64 + h + 1];
            lg2 += a0 * w2a[128 + h] + a1 * w2a[128 + h + 1];
            vv  += c0 * w2c[h]       + c1 * w2c[h + 1];
        }
    }
    float4* scr = reinterpret_cast<float4*>(ht);
    scr[bL * 4 + part] = make_float4(lg0, lg1, lg2, vv);
    __syncthreads();
    if (part == 0) {
        float4 s0 = scr[bL * 4], s1 = scr[bL * 4 + 1], s2 = scr[bL * 4 + 2], s3 = scr[bL * 4 + 3];
        float l0 = s0.x + s1.x + s2.x + s3.x + sm[8576];
        float l1 = s0.y + s1.y + s2.y + s3.y + sm[8577];
        float l2 = s0.z + s1.z + s2.z + s3.z + sm[8578];
        float vt = s0.w + s1.w + s2.w + s3.w + sm[8579];
        float m = fmaxf(l0, fmaxf(l1, l2));
        float s = __expf(l0 - m) + __expf(l1 - m) + __expf(l2 - m);
        float lse = m + __logf(s);
        int b = tb + bL;
        out[b * 3 + 0] = l0 - lse;
        out[b * 3 + 1] = l1 - lse;
        out[b * 3 + 2] = l2 - lse;
        out[(size_t)3 * BATCH + b] = vt;
    }
}

// ---------------- launch ----------------
extern "C" void kernel_launch(void* const* d_in, const int* in_sizes, int n_in,
                              void* d_out, int out_size) {
    Params P;
    for (int i = 0; i < 32; i++) P.p[i] = (const float*)d_in[i];
    float* out = (float*)d_out;

    cudaFuncSetAttribute(gru_kernel, cudaFuncAttributeMaxDynamicSharedMemorySize,
                         GRU_SMEM_FLOATS * 4);
    cudaFuncSetAttribute(conv_kernel, cudaFuncAttributeMaxDynamicSharedMemorySize,
                         CONV_SMEM_FLOATS * 4);

    prep_kernel<<<422, 256>>>(P);
    transpose_kernel<<<dim3(BATCH / 32, 8), dim3(32, 8)>>>(P.p[1]);
    conv_kernel<<<BATCH / 256, 256, CONV_SMEM_FLOATS * 4>>>(
        P.p[0], P.p[2], P.p[3], P.p[4], P.p[5], P.p[6], P.p[7]);
    gru_kernel<<<BATCH / 64, 256, GRU_SMEM_FLOATS * 4>>>(out);
}

// round 9
// speedup vs baseline: 2.0972x; 1.4750x over previous
#include <cuda_runtime.h>
#include <cstdint>

#define BATCH 65536
typedef unsigned long long u64;

// ---------------- static device scratch (no allocations) ----------------
__device__ __align__(16) float g_x[64 * BATCH];    // conv embedding, transposed [k][B]
__device__ __align__(16) float g_h[256 * BATCH];   // memory transposed [j][B]
__device__ __align__(16) float g_p1[144 * BATCH];  // conv1+pool out, [ic*9+pos][B]
__device__ __align__(16) float g_wt[98304];        // [cell][side(x/h)][k][gate3][pair32][2]
__device__ __align__(16) float g_bias[1024];       // [cell][{r,z,ni,nh}][64]
__device__ __align__(16) float g_heads[8580];      // [k][64 pair-floats] + w2/b
struct Params { const float* p[32]; };

// ---------------- f32x2 helpers ----------------
__device__ __forceinline__ void ffma2(u64& acc, u64 w, u64 x) {
    asm("fma.rn.f32x2 %0, %1, %2, %0;" : "+l"(acc) : "l"(w), "l"(x));
}
__device__ __forceinline__ u64 pack2(float a, float b) {
    u64 r; asm("mov.b64 %0, {%1, %2};" : "=l"(r) : "f"(a), "f"(b)); return r;
}
__device__ __forceinline__ void unpack2(u64 v, float& a, float& b) {
    asm("mov.b64 {%0, %1}, %2;" : "=f"(a), "=f"(b) : "l"(v));
}
__device__ __forceinline__ float sigm(float v) {
    return __fdividef(1.f, 1.f + __expf(-v));
}
__device__ __forceinline__ float tanh_fast(float v) {
    float e = __expf(2.f * v);
    return 1.f - __fdividef(2.f, e + 1.f);
}

// ---------------- prep: weight transposition ----------------
__global__ void prep_kernel(Params P) {
    int t = blockIdx.x * blockDim.x + threadIdx.x;
    if (t < 98304) {
        int cell = t / 24576, r1 = t % 24576;
        int side = r1 / 12288, r2 = r1 % 12288;
        int k    = r2 / 192,   r3 = r2 % 192;
        int g    = r3 / 64,    j  = r3 % 64;
        const float* src = P.p[8 + cell * 4 + side];  // wih, whh
        g_wt[t] = src[(g * 64 + j) * 64 + k];
    } else if (t < 99328) {
        int u = t - 98304;
        int cell = u / 256, v = u % 256;
        int g4 = v / 64, j = v % 64;
        const float* bih = P.p[10 + cell * 4];
        const float* bhh = P.p[11 + cell * 4];
        float val;
        if      (g4 == 0) val = bih[j]       + bhh[j];
        else if (g4 == 1) val = bih[64 + j]  + bhh[64 + j];
        else if (g4 == 2) val = bih[128 + j];
        else              val = bhh[128 + j];
        g_bias[u] = val;
    } else if (t < 107908) {
        int u = t - 99328;
        float val;
        if (u < 8192) {        // w1: [k][128] : pairs 0..31 actor, 32..63 critic
            int k = u / 128, f = u % 128;
            int pair = f / 2, half = f & 1;
            if (pair < 32) val = P.p[24][(2 * pair + half) * 64 + k];
            else           val = P.p[28][(2 * (pair - 32) + half) * 64 + k];
        }
        else if (u < 8384) val = P.p[26][u - 8192];   // actor_w2 [3][64]
        else if (u < 8448) val = P.p[30][u - 8384];   // critic_w2 [64]
        else if (u < 8512) val = P.p[25][u - 8448];   // actor_b1
        else if (u < 8576) val = P.p[29][u - 8512];   // critic_b1
        else if (u < 8579) val = P.p[27][u - 8576];   // actor_b2
        else               val = P.p[31][0];          // critic_b2
        g_heads[u] = val;
    }
}

// ---------------- transpose: mem [B][256] -> g_h [256][B] ----------------
__global__ void transpose_kernel(const float* __restrict__ mem) {
    __shared__ float tile[32][33];
    int jb = blockIdx.y * 32;
    int bb = blockIdx.x * 32;
    int tx = threadIdx.x, ty = threadIdx.y;
#pragma unroll
    for (int r = ty; r < 32; r += 8)
        tile[r][tx] = mem[(size_t)(bb + r) * 256 + jb + tx];
    __syncthreads();
#pragma unroll
    for (int r = ty; r < 32; r += 8)
        g_h[(size_t)(jb + r) * BATCH + bb + tx] = tile[tx][r];
}

// ---------------- conv_a: conv1 + pool -> g_p1 (spill-free) ----------------
// smem: obs 37632 | w1 192 | b1 16 = 37840 floats
#define CONVA_SMEM_FLOATS 37840
__global__ __launch_bounds__(256, 1)
void conv_a_kernel(const float* __restrict__ obs,
                   const float* __restrict__ w1, const float* __restrict__ b1) {
    extern __shared__ __align__(16) float cs[];
    float* obs_s = cs;
    float* sw1 = cs + 37632;
    float* sb1 = cs + 37824;
    int tid = threadIdx.x;

    {
        const float4* src = reinterpret_cast<const float4*>(obs) + (size_t)blockIdx.x * 9408;
        float4* dst = reinterpret_cast<float4*>(obs_s);
        for (int i = tid; i < 9408; i += 256) dst[i] = src[i];
    }
    for (int i = tid; i < 192; i += 256) sw1[i] = w1[i];
    if (tid < 16) sb1[tid] = b1[tid];
    __syncthreads();

    int b = blockIdx.x * 256 + tid;
    const float* ob = obs_s + tid * 147;

#pragma unroll
    for (int py = 0; py < 3; py++) {
#pragma unroll
        for (int px = 0; px < 3; px++) {
            float w[3][3][3];
#pragma unroll
            for (int dy = 0; dy < 3; dy++)
#pragma unroll
                for (int dx = 0; dx < 3; dx++)
#pragma unroll
                    for (int c = 0; c < 3; c++)
                        w[dy][dx][c] = ob[((2 * py + dy) * 7 + (2 * px + dx)) * 3 + c];
#pragma unroll
            for (int oc = 0; oc < 16; oc++) {
                float wk[12];
#pragma unroll
                for (int i = 0; i < 12; i++) wk[i] = sw1[oc * 12 + i];
                float bb = sb1[oc];
                float m = 0.f;  // ReLU folded into pool
#pragma unroll
                for (int a = 0; a < 2; a++) {
#pragma unroll
                    for (int bb2 = 0; bb2 < 2; bb2++) {
                        float v = bb;
#pragma unroll
                        for (int c = 0; c < 3; c++)
#pragma unroll
                            for (int ky = 0; ky < 2; ky++)
#pragma unroll
                                for (int kx = 0; kx < 2; kx++)
                                    v += w[a + ky][bb2 + kx][c] * wk[c * 4 + ky * 2 + kx];
                        m = fmaxf(m, v);
                    }
                }
                g_p1[(size_t)(oc * 9 + py * 3 + px) * BATCH + b] = m;
            }
        }
    }
}

// ---------------- conv_b: conv2 (gather) + conv3 -> g_x (spill-free) ----------------
// smem: w2t [64][32] 2048 | b2 32 | w3 8192 | b3 64 = 10336 floats
#define CONVB_SMEM_FLOATS 10336
__global__ __launch_bounds__(256, 1)
void conv_b_kernel(const float* __restrict__ w2, const float* __restrict__ b2,
                   const float* __restrict__ w3, const float* __restrict__ b3) {
    extern __shared__ __align__(16) float cb[];
    float* sw2t = cb;                  // [widx=ic*4+dy*2+dx][oc]
    float* sb2 = cb + 2048;
    float* sw3 = cb + 2080;
    float* sb3 = cb + 10272;
    int tid = threadIdx.x;

    for (int i = tid; i < 2048; i += 256) {
        int widx = i >> 5, oc = i & 31;
        sw2t[i] = w2[oc * 64 + widx];
    }
    if (tid < 32) sb2[tid] = b2[tid];
    for (int i = tid; i < 8192; i += 256) sw3[i] = w3[i];
    if (tid < 64) sb3[tid] = b3[tid];
    __syncthreads();

    int b = blockIdx.x * 256 + tid;

    float c2[32][4];
#pragma unroll
    for (int oc = 0; oc < 32; oc++)
#pragma unroll
        for (int q = 0; q < 4; q++) c2[oc][q] = sb2[oc];

    // conv2 gather: c2[oc][qy,qx] += p1[ic][qy+dy][qx+dx] * w2[oc][ic][dy][dx]
#pragma unroll 2
    for (int ic = 0; ic < 16; ic++) {
        float p[9];
#pragma unroll
        for (int pos = 0; pos < 9; pos++)
            p[pos] = g_p1[(size_t)(ic * 9 + pos) * BATCH + b];
#pragma unroll
        for (int dy = 0; dy < 2; dy++) {
#pragma unroll
            for (int dx = 0; dx < 2; dx++) {
                const float4* wrow = reinterpret_cast<const float4*>(
                    sw2t + (ic * 4 + dy * 2 + dx) * 32);
                float4 wv[8];
#pragma unroll
                for (int o4 = 0; o4 < 8; o4++) wv[o4] = wrow[o4];
#pragma unroll
                for (int q = 0; q < 4; q++) {
                    int qy = q >> 1, qx = q & 1;
                    float pv = p[(qy + dy) * 3 + (qx + dx)];
#pragma unroll
                    for (int o4 = 0; o4 < 8; o4++) {
                        c2[o4 * 4 + 0][q] += pv * wv[o4].x;
                        c2[o4 * 4 + 1][q] += pv * wv[o4].y;
                        c2[o4 * 4 + 2][q] += pv * wv[o4].z;
                        c2[o4 * 4 + 3][q] += pv * wv[o4].w;
                    }
                }
            }
        }
    }
#pragma unroll
    for (int oc = 0; oc < 32; oc++)
#pragma unroll
        for (int q = 0; q < 4; q++) c2[oc][q] = fmaxf(c2[oc][q], 0.f);

    // conv3 (2x2 on 2x2 -> 1x1, 32->64) + ReLU, write transposed
    const float4* sw3_4 = reinterpret_cast<const float4*>(sw3);
#pragma unroll
    for (int oc = 0; oc < 64; oc++) {
        float a0 = sb3[oc], a1 = 0.f;
#pragma unroll
        for (int ic = 0; ic < 32; ic += 2) {
            float4 wv = sw3_4[oc * 32 + ic];
            a0 += c2[ic][0] * wv.x; a0 += c2[ic][1] * wv.y;
            a0 += c2[ic][2] * wv.z; a0 += c2[ic][3] * wv.w;
            float4 wu = sw3_4[oc * 32 + ic + 1];
            a1 += c2[ic + 1][0] * wu.x; a1 += c2[ic + 1][1] * wu.y;
            a1 += c2[ic + 1][2] * wu.z; a1 += c2[ic + 1][3] * wu.w;
        }
        g_x[oc * BATCH + b] = fmaxf(a0 + a1, 0.f);
    }
}

// ---------------- GRU x4 + heads : register-tiled GEMM, 2 CTAs/SM ----------------
// smem: W 12288 | x_tile 4096 | h_tile 4096 | bias 256 = 20736 floats (83 KB)
#define GRU_SMEM_FLOATS 20736
__global__ __launch_bounds__(256, 2)
void gru_kernel(float* __restrict__ out) {
    extern __shared__ __align__(16) float sm[];
    float* xt = sm + 12288;
    float* ht = sm + 16384;
    float* bias = sm + 20480;
    int tid = threadIdx.x;
    int tj = tid >> 4, bq = tid & 15;        // thread: j = 4*tj..4*tj+3, b = bq*4..bq*4+3
    int tb = blockIdx.x * 64;

    { // stage x_tile from g_x (coalesced)
        float4* dst = reinterpret_cast<float4*>(xt);
        for (int i = tid; i < 1024; i += 256) {
            int row = i >> 4, c4 = i & 15;
            dst[i] = *reinterpret_cast<const float4*>(&g_x[row * BATCH + tb + c4 * 4]);
        }
    }

    for (int cell = 0; cell < 4; cell++) {
        __syncthreads();
        { // stage Wx + h_tile + bias
            const float4* src = reinterpret_cast<const float4*>(g_wt + cell * 24576);
            float4* dst = reinterpret_cast<float4*>(sm);
            for (int i = tid; i < 3072; i += 256) dst[i] = src[i];
            float4* hdst = reinterpret_cast<float4*>(ht);
            for (int i = tid; i < 1024; i += 256) {
                int row = i >> 4, c4 = i & 15;
                hdst[i] = *reinterpret_cast<const float4*>(
                    &g_h[(size_t)(cell * 64 + row) * BATCH + tb + c4 * 4]);
            }
            if (tid < 64)
                reinterpret_cast<float4*>(bias)[tid] =
                    reinterpret_cast<const float4*>(g_bias + cell * 256)[tid];
        }
        __syncthreads();

        u64 ar[2][4], az[2][4], an[2][4], ah[2][4];
        {
            const u64* bs = reinterpret_cast<const u64*>(bias);
#pragma unroll
            for (int p = 0; p < 2; p++) {
                u64 vr = bs[      2 * tj + p];
                u64 vz = bs[32 +  2 * tj + p];
                u64 vn = bs[64 +  2 * tj + p];
                u64 vh = bs[96 +  2 * tj + p];
#pragma unroll
                for (int b = 0; b < 4; b++) { ar[p][b] = vr; az[p][b] = vz; an[p][b] = vn; ah[p][b] = vh; }
            }
        }

        const ulonglong2* W = reinterpret_cast<const ulonglong2*>(sm);
        const float4* xt4 = reinterpret_cast<const float4*>(xt);
        const float4* ht4 = reinterpret_cast<const float4*>(ht);

        // x-pass: r, z, ni
#pragma unroll 2
        for (int k = 0; k < 64; k++) {
            float4 xv = xt4[k * 16 + bq];
            u64 xp[4] = {pack2(xv.x, xv.x), pack2(xv.y, xv.y), pack2(xv.z, xv.z), pack2(xv.w, xv.w)};
            ulonglong2 wr = W[k * 48 +      tj];
            ulonglong2 wz = W[k * 48 + 16 + tj];
            ulonglong2 wn = W[k * 48 + 32 + tj];
            u64 wrp[2] = {wr.x, wr.y}, wzp[2] = {wz.x, wz.y}, wnp[2] = {wn.x, wn.y};
#pragma unroll
            for (int p = 0; p < 2; p++)
#pragma unroll
                for (int b = 0; b < 4; b++) {
                    ffma2(ar[p][b], wrp[p], xp[b]);
                    ffma2(az[p][b], wzp[p], xp[b]);
                    ffma2(an[p][b], wnp[p], xp[b]);
                }
        }

        __syncthreads();   // Wx reads done before overwrite with Wh
        { // stage Wh
            const float4* src = reinterpret_cast<const float4*>(g_wt + cell * 24576 + 12288);
            float4* dst = reinterpret_cast<float4*>(sm);
            for (int i = tid; i < 3072; i += 256) dst[i] = src[i];
        }
        __syncthreads();

        // h-pass: r, z, nh
#pragma unroll 2
        for (int k = 0; k < 64; k++) {
            float4 hv = ht4[k * 16 + bq];
            u64 hp[4] = {pack2(hv.x, hv.x), pack2(hv.y, hv.y), pack2(hv.z, hv.z), pack2(hv.w, hv.w)};
            ulonglong2 wr = W[k * 48 +      tj];
            ulonglong2 wz = W[k * 48 + 16 + tj];
            ulonglong2 wn = W[k * 48 + 32 + tj];
            u64 wrp[2] = {wr.x, wr.y}, wzp[2] = {wz.x, wz.y}, wnp[2] = {wn.x, wn.y};
#pragma unroll
            for (int p = 0; p < 2; p++)
#pragma unroll
                for (int b = 0; b < 4; b++) {
                    ffma2(ar[p][b], wrp[p], hp[b]);
                    ffma2(az[p][b], wzp[p], hp[b]);
                    ffma2(ah[p][b], wnp[p], hp[b]);
                }
        }

        __syncthreads();   // all xt reads (x-pass) done; safe to overwrite below
        // finalize
        float hpa[4][4];
#pragma unroll
        for (int jj = 0; jj < 4; jj++) {
            float4 hv = ht4[(4 * tj + jj) * 16 + bq];
            hpa[jj][0] = hv.x; hpa[jj][1] = hv.y; hpa[jj][2] = hv.z; hpa[jj][3] = hv.w;
        }
        float o[4][4];
#pragma unroll
        for (int p = 0; p < 2; p++) {
#pragma unroll
            for (int b = 0; b < 4; b++) {
                float r0, r1, z0, z1, n0, n1, q0, q1;
                unpack2(ar[p][b], r0, r1); unpack2(az[p][b], z0, z1);
                unpack2(an[p][b], n0, n1); unpack2(ah[p][b], q0, q1);
                float rr0 = sigm(r0), rr1 = sigm(r1);
                float zz0 = sigm(z0), zz1 = sigm(z1);
                float nn0 = tanh_fast(n0 + rr0 * q0);
                float nn1 = tanh_fast(n1 + rr1 * q1);
                o[2 * p][b]     = (1.f - zz0) * nn0 + zz0 * hpa[2 * p][b];
                o[2 * p + 1][b] = (1.f - zz1) * nn1 + zz1 * hpa[2 * p + 1][b];
            }
        }
        float4* xtw = reinterpret_cast<float4*>(xt);
#pragma unroll
        for (int jj = 0; jj < 4; jj++)
            xtw[(4 * tj + jj) * 16 + bq] = make_float4(o[jj][0], o[jj][1], o[jj][2], o[jj][3]);
#pragma unroll
        for (int b = 0; b < 4; b++) {
            size_t gb = (size_t)(tb + bq * 4 + b);
            *reinterpret_cast<float4*>(&out[(size_t)4 * BATCH + gb * 256 + cell * 64 + 4 * tj]) =
                make_float4(o[0][b], o[1][b], o[2][b], o[3][b]);
        }
    }

    // ---------------- heads ----------------
    __syncthreads();
    { // stage head weights into W region
        const float4* src = reinterpret_cast<const float4*>(g_heads);
        float4* dst = reinterpret_cast<float4*>(sm);
        for (int i = tid; i < 2145; i += 256) dst[i] = src[i];
    }
    __syncthreads();

    int bL = tid >> 2, part = tid & 3;      // b = tb+bL ; h-range = part*16..+16
    u64 aa[8], cc[8];
    {
        const u64* ba = reinterpret_cast<const u64*>(sm + 8448);
        const u64* bc = reinterpret_cast<const u64*>(sm + 8512);
#pragma unroll
        for (int i = 0; i < 8; i++) { aa[i] = ba[part * 8 + i]; cc[i] = bc[part * 8 + i]; }
    }
    const ulonglong2* w1 = reinterpret_cast<const ulonglong2*>(sm);
#pragma unroll 2
    for (int k = 0; k < 64; k++) {
        float xv = xt[k * 64 + bL];
        u64 xp = pack2(xv, xv);
        const ulonglong2* row = w1 + k * 32;
#pragma unroll
        for (int i2 = 0; i2 < 4; i2++) {
            ulonglong2 wa = row[part * 4 + i2];
            ffma2(aa[i2 * 2], wa.x, xp); ffma2(aa[i2 * 2 + 1], wa.y, xp);
            ulonglong2 wc = row[16 + part * 4 + i2];
            ffma2(cc[i2 * 2], wc.x, xp); ffma2(cc[i2 * 2 + 1], wc.y, xp);
        }
    }
    float lg0 = 0.f, lg1 = 0.f, lg2 = 0.f, vv = 0.f;
    {
        const float* w2a = sm + 8192;
        const float* w2c = sm + 8384;
#pragma unroll
        for (int i = 0; i < 8; i++) {
            float a0, a1, c0, c1;
            unpack2(aa[i], a0, a1); unpack2(cc[i], c0, c1);
            a0 = fmaxf(a0, 0.f); a1 = fmaxf(a1, 0.f);
            c0 = fmaxf(c0, 0.f); c1 = fmaxf(c1, 0.f);
            int h = part * 16 + 2 * i;
            lg0 += a0 * w2a[h]       + a1 * w2a[h + 1];
            lg1 += a0 * w2a[64 + h]  + a1 * w2a[64 + h + 1];
            lg2 += a0 * w2a[128 + h] + a1 * w2a[128 + h + 1];
            vv  += c0 * w2c[h]       + c1 * w2c[h + 1];
        }
    }
    float4* scr = reinterpret_cast<float4*>(ht);
    scr[bL * 4 + part] = make_float4(lg0, lg1, lg2, vv);
    __syncthreads();
    if (part == 0) {
        float4 s0 = scr[bL * 4], s1 = scr[bL * 4 + 1], s2 = scr[bL * 4 + 2], s3 = scr[bL * 4 + 3];
        float l0 = s0.x + s1.x + s2.x + s3.x + sm[8576];
        float l1 = s0.y + s1.y + s2.y + s3.y + sm[8577];
        float l2 = s0.z + s1.z + s2.z + s3.z + sm[8578];
        float vt = s0.w + s1.w + s2.w + s3.w + sm[8579];
        float m = fmaxf(l0, fmaxf(l1, l2));
        float s = __expf(l0 - m) + __expf(l1 - m) + __expf(l2 - m);
        float lse = m + __logf(s);
        int b = tb + bL;
        out[b * 3 + 0] = l0 - lse;
        out[b * 3 + 1] = l1 - lse;
        out[b * 3 + 2] = l2 - lse;
        out[(size_t)3 * BATCH + b] = vt;
    }
}

// ---------------- launch ----------------
extern "C" void kernel_launch(void* const* d_in, const int* in_sizes, int n_in,
                              void* d_out, int out_size) {
    Params P;
    for (int i = 0; i < 32; i++) P.p[i] = (const float*)d_in[i];
    float* out = (float*)d_out;

    cudaFuncSetAttribute(gru_kernel, cudaFuncAttributeMaxDynamicSharedMemorySize,
                         GRU_SMEM_FLOATS * 4);
    cudaFuncSetAttribute(conv_a_kernel, cudaFuncAttributeMaxDynamicSharedMemorySize,
                         CONVA_SMEM_FLOATS * 4);
    cudaFuncSetAttribute(conv_b_kernel, cudaFuncAttributeMaxDynamicSharedMemorySize,
                         CONVB_SMEM_FLOATS * 4);

    prep_kernel<<<422, 256>>>(P);
    transpose_kernel<<<dim3(BATCH / 32, 8), dim3(32, 8)>>>(P.p[1]);
    conv_a_kernel<<<BATCH / 256, 256, CONVA_SMEM_FLOATS * 4>>>(P.p[0], P.p[2], P.p[3]);
    conv_b_kernel<<<BATCH / 256, 256, CONVB_SMEM_FLOATS * 4>>>(P.p[4], P.p[5], P.p[6], P.p[7]);
    gru_kernel<<<BATCH / 64, 256, GRU_SMEM_FLOATS * 4>>>(out);
}